// round 9
// baseline (speedup 1.0000x reference)
#include <cuda_runtime.h>
#include <math.h>

#define N_PTS 65536
#define KKEY 64
#define NT 256
#define GRID_SCORE 256   // 256 blocks x 128 pairs = 65536 points

typedef unsigned long long u64;

// scratch (no allocations allowed) — referenced ONLY from device code
__device__ u64 g_cand[GRID_SCORE * KKEY];   // 16384
__device__ u64 g_cand2[16 * KKEY];          // 1024

// ---------------------------------------------------------------------------
// packed f32x2 helpers (FFMA2: 2 fp32 FMAs per instruction, only via PTX)
// ---------------------------------------------------------------------------
__device__ __forceinline__ u64 fma2(u64 a, u64 b, u64 c) {
    u64 d;
    asm("fma.rn.f32x2 %0, %1, %2, %3;" : "=l"(d) : "l"(a), "l"(b), "l"(c));
    return d;
}
__device__ __forceinline__ u64 add2(u64 a, u64 b) {
    u64 d;
    asm("add.rn.f32x2 %0, %1, %2;" : "=l"(d) : "l"(a), "l"(b));
    return d;
}
__device__ __forceinline__ u64 pack2(float lo, float hi) {
    u64 r;
    asm("mov.b64 %0, {%1, %2};" : "=l"(r) : "f"(lo), "f"(hi));
    return r;
}
__device__ __forceinline__ void unpack2(u64 x, float& lo, float& hi) {
    asm("mov.b64 {%0, %1}, %2;" : "=f"(lo), "=f"(hi) : "l"(x));
}
__device__ __forceinline__ u64 relu2(u64 x) {
    float lo, hi;
    unpack2(x, lo, hi);
    return pack2(fmaxf(lo, 0.0f), fmaxf(hi, 0.0f));
}

// ---------------------------------------------------------------------------
// bitonic compare-select, element at global position i, descending sort.
// Keys unique (low bits = ~index) so strict compare is fine.
// ---------------------------------------------------------------------------
__device__ __forceinline__ u64 cmpsel(u64 v, u64 pv, int i, int k, int j) {
    bool keep_max = (((i & k) == 0) == ((i & j) == 0));
    u64 mx = v > pv ? v : pv;
    u64 mn = v > pv ? pv : v;
    return keep_max ? mx : mn;
}

// ---------------------------------------------------------------------------
// Kernel 1: MLP score (batch 0), point-pair split across 2 threads (k-split),
// then in-block sort of the block's 256 keys -> emit block top-64.
// key = (bits(softplus) << 32) | ~n  (sp > 0 so bits are order-monotonic)
// ---------------------------------------------------------------------------
__global__ __launch_bounds__(NT, 2) void score_kernel(
    const float* __restrict__ src,
    const float* __restrict__ W1, const float* __restrict__ b1,
    const float* __restrict__ W2, const float* __restrict__ b2,
    const float* __restrict__ Wa, const float* __restrict__ ba,
    const float* __restrict__ Wb, const float* __restrict__ bb_,
    const float* __restrict__ Wc, const float* __restrict__ bc)
{
    // weights duplicated into both f32 halves of a u64; Wa stored transposed
    __shared__ __align__(16) u64 sW1[192];
    __shared__ __align__(16) u64 sW2[2048];
    __shared__ __align__(16) u64 sWaT[1024];   // sWaT[j*16+i] = Wa[i*64+j]
    __shared__ __align__(16) u64 sWb[128];
    __shared__ __align__(16) u64 sWc[8];
    __shared__ u64 sb1[32];
    __shared__ u64 sb2[64];
    __shared__ u64 sba[16];
    __shared__ u64 sbb[8];
    __shared__ u64 sbc;
    __shared__ u64 s_keys[256];

    const int t = threadIdx.x;
    const int blk = blockIdx.x;
    const int p = t & 1;          // parity: which half of the network
    const int pr = t >> 1;        // pair index within block (0..127)

#define DUP(w) ( ((u64)__float_as_uint(w)) * 0x100000001ULL )
    for (int i = t; i < 2048; i += NT) sW2[i] = DUP(W2[i]);
    for (int idx = t; idx < 1024; idx += NT) {
        int j = idx >> 4, i = idx & 15;
        sWaT[idx] = DUP(Wa[i * 64 + j]);
    }
    if (t < 192) sW1[t] = DUP(W1[t]);
    if (t < 128) sWb[t] = DUP(Wb[t]);
    if (t < 64)  sb2[t] = DUP(b2[t]);
    if (t < 32)  sb1[t] = DUP(b1[t]);
    if (t < 16)  sba[t] = DUP(ba[t]);
    if (t < 8)   sbb[t] = DUP(bb_[t]);
    if (t < 8)   sWc[t] = DUP(Wc[t]);
    if (t == 0)  sbc = DUP(bc[0]);
#undef DUP
    __syncthreads();

    const int gpair = blk * 128 + pr;
    const int n0 = 2 * gpair;     // points n0, n0+1 (both threads of the pair)

    u64 x[6];
#pragma unroll
    for (int c = 0; c < 6; c++) {
        float2 v = *(const float2*)(src + c * N_PTS + n0);
        x[c] = pack2(v.x, v.y);
    }

    // layer 1: this thread computes h1 neurons [16p, 16p+16)
    u64 h1[16];
#pragma unroll
    for (int i = 0; i < 16; i++) {
        const int ii = p * 16 + i;
        const ulonglong2* w = (const ulonglong2*)(sW1 + ii * 6);
        ulonglong2 q0 = w[0], q1 = w[1], q2 = w[2];
        u64 v = sb1[ii];
        v = fma2(q0.x, x[0], v);
        v = fma2(q0.y, x[1], v);
        v = fma2(q1.x, x[2], v);
        v = fma2(q1.y, x[3], v);
        v = fma2(q2.x, x[4], v);
        v = fma2(q2.y, x[5], v);
        h1[i] = relu2(v);
    }

    // layer 2 (32->64, relu) + layer a (64->16): k-split across the pair.
    // Thread p sums k in [16p,16p+16); exchange partials; both get full v.
    // Thread p accumulates a-outputs i in [8p, 8p+8).
    u64 a[8];
#pragma unroll
    for (int i = 0; i < 8; i++) a[i] = sba[p * 8 + i];

#pragma unroll 2
    for (int j = 0; j < 64; j++) {
        const ulonglong2* w2 = (const ulonglong2*)(sW2 + j * 32 + p * 16);
        u64 a0 = p ? 0ULL : sb2[j];   // bias folded into even-half partial
        u64 a1 = 0ULL;
#pragma unroll
        for (int k = 0; k < 16; k += 4) {
            ulonglong2 q0 = w2[k / 2];
            ulonglong2 q1 = w2[k / 2 + 1];
            a0 = fma2(q0.x, h1[k],     a0);
            a1 = fma2(q0.y, h1[k + 1], a1);
            a0 = fma2(q1.x, h1[k + 2], a0);
            a1 = fma2(q1.y, h1[k + 3], a1);
        }
        u64 part = add2(a0, a1);
        u64 other = __shfl_xor_sync(0xffffffffu, part, 1);
        // deterministic order: (even-half) + (odd-half) on both threads
        u64 v = relu2(p ? add2(other, part) : add2(part, other));

        const ulonglong2* wa = (const ulonglong2*)(sWaT + j * 16 + p * 8);
#pragma unroll
        for (int i = 0; i < 8; i += 2) {
            ulonglong2 q = wa[i / 2];
            a[i]     = fma2(q.x, v, a[i]);
            a[i + 1] = fma2(q.y, v, a[i + 1]);
        }
    }
#pragma unroll
    for (int i = 0; i < 8; i++) a[i] = relu2(a[i]);

    // gather full a[16] onto the even thread (odd's result discarded)
    u64 afull[16];
#pragma unroll
    for (int i = 0; i < 8; i++) {
        u64 recv = __shfl_xor_sync(0xffffffffu, a[i], 1);
        afull[i]     = p ? recv : a[i];     // even half (i in 0..8)
        afull[8 + i] = p ? a[i] : recv;     // odd half  (i in 8..16)
    }

    if (p == 0) {
        // layer b: 16 -> 8, relu (2-way split chains, R6 order)
        u64 hb[8];
#pragma unroll
        for (int i = 0; i < 8; i++) {
            const ulonglong2* wb = (const ulonglong2*)(sWb + i * 16);
            u64 s0 = sbb[i], s1 = 0ULL;
#pragma unroll
            for (int k = 0; k < 16; k += 4) {
                ulonglong2 q0 = wb[k / 2];
                ulonglong2 q1 = wb[k / 2 + 1];
                s0 = fma2(q0.x, afull[k],     s0);
                s1 = fma2(q0.y, afull[k + 1], s1);
                s0 = fma2(q1.x, afull[k + 2], s0);
                s1 = fma2(q1.y, afull[k + 3], s1);
            }
            hb[i] = relu2(add2(s0, s1));
        }

        // layer c: 8 -> 1, softplus = max(x,0)+log1p(exp(-|x|))
        u64 c2 = sbc;
#pragma unroll
        for (int k = 0; k < 8; k++) c2 = fma2(sWc[k], hb[k], c2);
        float c0, c1;
        unpack2(c2, c0, c1);
        float sp0 = fmaxf(c0, 0.0f) + log1pf(expf(-fabsf(c0)));
        float sp1 = fmaxf(c1, 0.0f) + log1pf(expf(-fabsf(c1)));

        s_keys[2 * pr]     = ((u64)__float_as_uint(sp0) << 32) | (unsigned int)(~n0);
        s_keys[2 * pr + 1] = ((u64)__float_as_uint(sp1) << 32) | (unsigned int)(~(n0 + 1));
    }
    __syncthreads();

    // in-block selection: sort the block's 256 keys (descending), keep top-64
    {
        u64 v = s_keys[t];
#pragma unroll
        for (int k = 2; k <= 256; k <<= 1) {
#pragma unroll
            for (int j = k >> 1; j > 0; j >>= 1) {
                u64 v2;
                if (j >= 32) {
                    __syncthreads();
                    s_keys[t] = v;
                    __syncthreads();
                    v2 = s_keys[t ^ j];
                } else {
                    v2 = __shfl_xor_sync(0xffffffffu, v, j);
                }
                v = cmpsel(v, v2, t, k, j);
            }
        }
        if (t < KKEY) g_cand[blk * KKEY + t] = v;
    }
}

// ---------------------------------------------------------------------------
// Stage: 16 blocks, each sorts 1024 of the 16384 candidates (descending),
// emits its top-64 -> 1024 survivors. 512 threads, 2 elems/thread.
// ---------------------------------------------------------------------------
__global__ __launch_bounds__(512) void stage_kernel()
{
    __shared__ u64 s[1024];
    const int t = threadIdx.x;
    const u64* p = g_cand + blockIdx.x * 1024;

    u64 v0 = p[t];
    u64 v1 = p[t + 512];

#pragma unroll
    for (int k = 2; k <= 1024; k <<= 1) {
#pragma unroll
        for (int j = k >> 1; j > 0; j >>= 1) {
            if (j >= 512) {
                bool keep_max = ((t & k) == 0);
                u64 mx = v0 > v1 ? v0 : v1;
                u64 mn = v0 > v1 ? v1 : v0;
                v0 = keep_max ? mx : mn;
                v1 = keep_max ? mn : mx;
            } else if (j >= 32) {
                __syncthreads();
                s[t] = v0;
                s[t + 512] = v1;
                __syncthreads();
                u64 p0 = s[t ^ j];
                u64 p1 = s[(t + 512) ^ j];
                v0 = cmpsel(v0, p0, t, k, j);
                v1 = cmpsel(v1, p1, t + 512, k, j);
            } else {
                u64 p0 = __shfl_xor_sync(0xffffffffu, v0, j);
                u64 p1 = __shfl_xor_sync(0xffffffffu, v1, j);
                v0 = cmpsel(v0, p0, t, k, j);
                v1 = cmpsel(v1, p1, t + 512, k, j);
            }
        }
    }

    if (t < KKEY) g_cand2[blockIdx.x * KKEY + t] = v0;
}

// ---------------------------------------------------------------------------
// Final: 1 block, 256 threads: sort the 1024 survivors (4 elems/thread),
// take top-64 indices, fused gather: out[b,k,c] = src_pts[b,c,idx[k]]
// ---------------------------------------------------------------------------
__global__ __launch_bounds__(256) void final_kernel(
    const float* __restrict__ src, float* __restrict__ out)
{
    __shared__ u64 s[1024];
    __shared__ int sidx[KKEY];
    const int t = threadIdx.x;

    u64 v[4];
#pragma unroll
    for (int m = 0; m < 4; m++) v[m] = g_cand2[t + 256 * m];

    for (int k = 2; k <= 1024; k <<= 1) {
        for (int j = k >> 1; j > 0; j >>= 1) {
            if (j >= 256) {
                int h = j >> 8;   // 1 or 2
#pragma unroll
                for (int m = 0; m < 4; m++) {
                    if (!(m & h)) {
                        int mp = m | h;
                        int i = t + (m << 8);
                        bool keep_max = ((i & k) == 0);
                        u64 a = v[m], b = v[mp];
                        u64 mx = a > b ? a : b;
                        u64 mn = a > b ? b : a;
                        v[m]  = keep_max ? mx : mn;
                        v[mp] = keep_max ? mn : mx;
                    }
                }
            } else if (j >= 32) {
                __syncthreads();
#pragma unroll
                for (int m = 0; m < 4; m++) s[t + 256 * m] = v[m];
                __syncthreads();
#pragma unroll
                for (int m = 0; m < 4; m++) {
                    int i = t + 256 * m;
                    v[m] = cmpsel(v[m], s[i ^ j], i, k, j);
                }
            } else {
#pragma unroll
                for (int m = 0; m < 4; m++) {
                    int i = t + 256 * m;
                    u64 pv = __shfl_xor_sync(0xffffffffu, v[m], j);
                    v[m] = cmpsel(v[m], pv, i, k, j);
                }
            }
        }
    }

    if (t < KKEY) sidx[t] = (int)(~(unsigned int)v[0]);
    __syncthreads();

    // out shape (8, 64, 6) row-major; 3072 elements
#pragma unroll
    for (int o = t; o < 8 * KKEY * 6; o += 256) {
        int c = o % 6;
        int k = (o / 6) & (KKEY - 1);
        int b = o / (6 * KKEY);
        out[o] = src[(b * 6 + c) * N_PTS + sidx[k]];
    }
}

// ---------------------------------------------------------------------------
extern "C" void kernel_launch(void* const* d_in, const int* in_sizes, int n_in,
                              void* d_out, int out_size)
{
    const float* src = (const float*)d_in[0];   // src_pts (8,6,65536)
    // d_in[1] = tgt_pts (unused)
    const float* W1 = (const float*)d_in[2];
    const float* b1 = (const float*)d_in[3];
    const float* W2 = (const float*)d_in[4];
    const float* b2 = (const float*)d_in[5];
    const float* Wa = (const float*)d_in[6];
    const float* ba = (const float*)d_in[7];
    const float* Wb = (const float*)d_in[8];
    const float* bb = (const float*)d_in[9];
    const float* Wc = (const float*)d_in[10];
    const float* bc = (const float*)d_in[11];
    float* out = (float*)d_out;

    score_kernel<<<GRID_SCORE, NT>>>(
        src, W1, b1, W2, b2, Wa, ba, Wb, bb, Wc, bc);
    stage_kernel<<<16, 512>>>();
    final_kernel<<<1, 256>>>(src, out);
}

// round 10
// speedup vs baseline: 1.2854x; 1.2854x over previous
#include <cuda_runtime.h>
#include <math.h>

#define N_PTS 65536
#define KKEY 64
#define NT 256
#define GRID_SCORE 256   // 256 blocks x 256 threads = 65536 points, 1 pt/thread

typedef unsigned long long u64;

// scratch (no allocations allowed) — referenced ONLY from device code
__device__ u64 g_cand[GRID_SCORE * KKEY];   // 16384
__device__ u64 g_cand2[16 * KKEY];          // 1024

// ---------------------------------------------------------------------------
// packed f32x2 helpers (FFMA2: 2 fp32 FMAs per instruction, only via PTX)
// ---------------------------------------------------------------------------
__device__ __forceinline__ u64 fma2(u64 a, u64 b, u64 c) {
    u64 d;
    asm("fma.rn.f32x2 %0, %1, %2, %3;" : "=l"(d) : "l"(a), "l"(b), "l"(c));
    return d;
}
__device__ __forceinline__ u64 add2(u64 a, u64 b) {
    u64 d;
    asm("add.rn.f32x2 %0, %1, %2;" : "=l"(d) : "l"(a), "l"(b));
    return d;
}
__device__ __forceinline__ u64 pack2(float lo, float hi) {
    u64 r;
    asm("mov.b64 %0, {%1, %2};" : "=l"(r) : "f"(lo), "f"(hi));
    return r;
}
__device__ __forceinline__ void unpack2(u64 x, float& lo, float& hi) {
    asm("mov.b64 {%0, %1}, %2;" : "=f"(lo), "=f"(hi) : "l"(x));
}
__device__ __forceinline__ u64 relu2(u64 x) {
    float lo, hi;
    unpack2(x, lo, hi);
    return pack2(fmaxf(lo, 0.0f), fmaxf(hi, 0.0f));
}

// ---------------------------------------------------------------------------
// bitonic compare-select, element at global position i, descending sort.
// Keys unique (low bits = ~index) so strict compare is fine.
// ---------------------------------------------------------------------------
__device__ __forceinline__ u64 cmpsel(u64 v, u64 pv, int i, int k, int j) {
    bool keep_max = (((i & k) == 0) == ((i & j) == 0));
    u64 mx = v > pv ? v : pv;
    u64 mn = v > pv ? pv : v;
    return keep_max ? mx : mn;
}

// ---------------------------------------------------------------------------
// Kernel 1: MLP score (batch 0), ONE point per thread; FFMA2 lanes carry two
// ADJACENT NEURONS (not two points). No cross-thread exchange.
// Then in-block sort of the block's 256 keys -> emit block top-64.
// key = (bits(softplus) << 32) | ~n  (sp > 0 so bits are order-monotonic)
// ---------------------------------------------------------------------------
__global__ __launch_bounds__(NT) void score_kernel(
    const float* __restrict__ src,
    const float* __restrict__ W1, const float* __restrict__ b1,
    const float* __restrict__ W2, const float* __restrict__ b2,
    const float* __restrict__ Wa, const float* __restrict__ ba,
    const float* __restrict__ Wb, const float* __restrict__ bb_,
    const float* __restrict__ Wc, const float* __restrict__ bc)
{
    // neuron-paired weight layouts
    __shared__ __align__(16) u64 sW1p[96];     // [i<16][c<6] = (W1[2i,c], W1[2i+1,c])
    __shared__ __align__(16) u64 sW2p[1024];   // [j<64][i<16] = (W2[j,2i], W2[j,2i+1])
    __shared__ __align__(16) u64 sWaTp[512];   // [j<64][i<8] = (Wa[2i,j], Wa[2i+1,j])
    __shared__ __align__(16) u64 sWbp[64];     // [i<4][k<16] = (Wb[2i,k], Wb[2i+1,k])
    __shared__ __align__(16) u64 sWcp[4];      // [i<4] = (Wc[2i], Wc[2i+1])
    __shared__ u64 sb1p[16];                   // (b1[2i], b1[2i+1])
    __shared__ float sb2[64];
    __shared__ u64 sbap[8];
    __shared__ u64 sbbp[4];
    __shared__ float sbc;
    __shared__ u64 s_keys[256];

    const int t = threadIdx.x;
    const int blk = blockIdx.x;

    // W2 rows are contiguous fp32 -> natural u64 pairs, direct copy
    for (int i = t; i < 1024; i += NT)
        sW2p[i] = ((const u64*)W2)[i];
    for (int idx = t; idx < 512; idx += NT) {
        int j = idx >> 3, i = idx & 7;
        sWaTp[idx] = pack2(Wa[(2 * i) * 64 + j], Wa[(2 * i + 1) * 64 + j]);
    }
    if (t < 96) {
        int i = t / 6, c = t % 6;
        sW1p[t] = pack2(W1[(2 * i) * 6 + c], W1[(2 * i + 1) * 6 + c]);
    }
    if (t >= 128 && t < 192) {
        int idx = t - 128;
        int i = idx >> 4, k = idx & 15;
        sWbp[idx] = pack2(Wb[(2 * i) * 16 + k], Wb[(2 * i + 1) * 16 + k]);
    }
    if (t >= 192 && t < 256) sb2[t - 192] = b2[t - 192];
    if (t >= 96 && t < 112)  sb1p[t - 96] = pack2(b1[2 * (t - 96)], b1[2 * (t - 96) + 1]);
    if (t >= 112 && t < 120) sbap[t - 112] = pack2(ba[2 * (t - 112)], ba[2 * (t - 112) + 1]);
    if (t >= 120 && t < 124) sbbp[t - 120] = pack2(bb_[2 * (t - 120)], bb_[2 * (t - 120) + 1]);
    if (t >= 124 && t < 128) sWcp[t - 124] = pack2(Wc[2 * (t - 124)], Wc[2 * (t - 124) + 1]);
    if (t == 0) sbc = bc[0];
    __syncthreads();

    const int n = blk * NT + t;   // point id

    u64 xd[6];
#pragma unroll
    for (int c = 0; c < 6; c++) {
        float xv = src[c * N_PTS + n];
        xd[c] = pack2(xv, xv);
    }

    // layer 1: 6 -> 32 (as 16 neuron-pairs), relu
    u64 h1p[16];
#pragma unroll
    for (int i = 0; i < 16; i++) {
        const ulonglong2* w = (const ulonglong2*)(sW1p + i * 6);
        ulonglong2 q0 = w[0], q1 = w[1], q2 = w[2];
        u64 v = sb1p[i];
        v = fma2(q0.x, xd[0], v);
        v = fma2(q0.y, xd[1], v);
        v = fma2(q1.x, xd[2], v);
        v = fma2(q1.y, xd[3], v);
        v = fma2(q2.x, xd[4], v);
        v = fma2(q2.y, xd[5], v);
        h1p[i] = relu2(v);
    }

    // layer 2 (32->64, relu) fused with layer a (64->16) accumulation
    u64 ap[8];
#pragma unroll
    for (int i = 0; i < 8; i++) ap[i] = sbap[i];

#pragma unroll 2
    for (int j = 0; j < 64; j++) {
        const ulonglong2* w2 = (const ulonglong2*)(sW2p + j * 16);
        u64 c0 = 0ULL, c1 = 0ULL, c2 = 0ULL, c3 = 0ULL;
#pragma unroll
        for (int i = 0; i < 16; i += 4) {
            ulonglong2 q0 = w2[i / 2];
            ulonglong2 q1 = w2[i / 2 + 1];
            c0 = fma2(q0.x, h1p[i],     c0);
            c1 = fma2(q0.y, h1p[i + 1], c1);
            c2 = fma2(q1.x, h1p[i + 2], c2);
            c3 = fma2(q1.y, h1p[i + 3], c3);
        }
        u64 s = add2(add2(c0, c1), add2(c2, c3));
        float lo, hi;
        unpack2(s, lo, hi);
        float v = fmaxf(sb2[j] + (lo + hi), 0.0f);
        u64 vd = pack2(v, v);

        const ulonglong2* wa = (const ulonglong2*)(sWaTp + j * 8);
#pragma unroll
        for (int i = 0; i < 8; i += 2) {
            ulonglong2 q = wa[i / 2];
            ap[i]     = fma2(q.x, vd, ap[i]);
            ap[i + 1] = fma2(q.y, vd, ap[i + 1]);
        }
    }
#pragma unroll
    for (int i = 0; i < 8; i++) ap[i] = relu2(ap[i]);

    // unpack a[16] and dup for layer b
    u64 afd[16];
#pragma unroll
    for (int i = 0; i < 8; i++) {
        float lo, hi;
        unpack2(ap[i], lo, hi);
        afd[2 * i]     = pack2(lo, lo);
        afd[2 * i + 1] = pack2(hi, hi);
    }

    // layer b: 16 -> 8 (as 4 neuron-pairs), relu
    u64 hbp[4];
#pragma unroll
    for (int i = 0; i < 4; i++) {
        const ulonglong2* wb = (const ulonglong2*)(sWbp + i * 16);
        u64 s0 = sbbp[i], s1 = 0ULL;
#pragma unroll
        for (int k = 0; k < 16; k += 4) {
            ulonglong2 q0 = wb[k / 2];
            ulonglong2 q1 = wb[k / 2 + 1];
            s0 = fma2(q0.x, afd[k],     s0);
            s1 = fma2(q0.y, afd[k + 1], s1);
            s0 = fma2(q1.x, afd[k + 2], s0);
            s1 = fma2(q1.y, afd[k + 3], s1);
        }
        hbp[i] = relu2(add2(s0, s1));
    }

    // layer c: 8 -> 1, softplus = max(x,0)+log1p(exp(-|x|))
    u64 cp = 0ULL;
#pragma unroll
    for (int i = 0; i < 4; i++) cp = fma2(sWcp[i], hbp[i], cp);
    float clo, chi;
    unpack2(cp, clo, chi);
    float c0f = sbc + (clo + chi);
    float sp = fmaxf(c0f, 0.0f) + log1pf(expf(-fabsf(c0f)));

    s_keys[t] = ((u64)__float_as_uint(sp) << 32) | (unsigned int)(~n);
    __syncthreads();

    // in-block selection: sort the block's 256 keys (descending), keep top-64
    {
        u64 v = s_keys[t];
#pragma unroll
        for (int k = 2; k <= 256; k <<= 1) {
#pragma unroll
            for (int j = k >> 1; j > 0; j >>= 1) {
                u64 v2;
                if (j >= 32) {
                    __syncthreads();
                    s_keys[t] = v;
                    __syncthreads();
                    v2 = s_keys[t ^ j];
                } else {
                    v2 = __shfl_xor_sync(0xffffffffu, v, j);
                }
                v = cmpsel(v, v2, t, k, j);
            }
        }
        if (t < KKEY) g_cand[blk * KKEY + t] = v;
    }
}

// ---------------------------------------------------------------------------
// Stage: 16 blocks, each sorts 1024 of the 16384 candidates (descending),
// emits its top-64 -> 1024 survivors. 512 threads, 2 elems/thread.
// ---------------------------------------------------------------------------
__global__ __launch_bounds__(512) void stage_kernel()
{
    __shared__ u64 s[1024];
    const int t = threadIdx.x;
    const u64* p = g_cand + blockIdx.x * 1024;

    u64 v0 = p[t];
    u64 v1 = p[t + 512];

#pragma unroll
    for (int k = 2; k <= 1024; k <<= 1) {
#pragma unroll
        for (int j = k >> 1; j > 0; j >>= 1) {
            if (j >= 512) {
                bool keep_max = ((t & k) == 0);
                u64 mx = v0 > v1 ? v0 : v1;
                u64 mn = v0 > v1 ? v1 : v0;
                v0 = keep_max ? mx : mn;
                v1 = keep_max ? mn : mx;
            } else if (j >= 32) {
                __syncthreads();
                s[t] = v0;
                s[t + 512] = v1;
                __syncthreads();
                u64 p0 = s[t ^ j];
                u64 p1 = s[(t + 512) ^ j];
                v0 = cmpsel(v0, p0, t, k, j);
                v1 = cmpsel(v1, p1, t + 512, k, j);
            } else {
                u64 p0 = __shfl_xor_sync(0xffffffffu, v0, j);
                u64 p1 = __shfl_xor_sync(0xffffffffu, v1, j);
                v0 = cmpsel(v0, p0, t, k, j);
                v1 = cmpsel(v1, p1, t + 512, k, j);
            }
        }
    }

    if (t < KKEY) g_cand2[blockIdx.x * KKEY + t] = v0;
}

// ---------------------------------------------------------------------------
// Final: 1 block, 256 threads: sort the 1024 survivors (4 elems/thread),
// take top-64 indices, fused gather: out[b,k,c] = src_pts[b,c,idx[k]]
// ---------------------------------------------------------------------------
__global__ __launch_bounds__(256) void final_kernel(
    const float* __restrict__ src, float* __restrict__ out)
{
    __shared__ u64 s[1024];
    __shared__ int sidx[KKEY];
    const int t = threadIdx.x;

    u64 v[4];
#pragma unroll
    for (int m = 0; m < 4; m++) v[m] = g_cand2[t + 256 * m];

    for (int k = 2; k <= 1024; k <<= 1) {
        for (int j = k >> 1; j > 0; j >>= 1) {
            if (j >= 256) {
                int h = j >> 8;   // 1 or 2
#pragma unroll
                for (int m = 0; m < 4; m++) {
                    if (!(m & h)) {
                        int mp = m | h;
                        int i = t + (m << 8);
                        bool keep_max = ((i & k) == 0);
                        u64 a = v[m], b = v[mp];
                        u64 mx = a > b ? a : b;
                        u64 mn = a > b ? b : a;
                        v[m]  = keep_max ? mx : mn;
                        v[mp] = keep_max ? mn : mx;
                    }
                }
            } else if (j >= 32) {
                __syncthreads();
#pragma unroll
                for (int m = 0; m < 4; m++) s[t + 256 * m] = v[m];
                __syncthreads();
#pragma unroll
                for (int m = 0; m < 4; m++) {
                    int i = t + 256 * m;
                    v[m] = cmpsel(v[m], s[i ^ j], i, k, j);
                }
            } else {
#pragma unroll
                for (int m = 0; m < 4; m++) {
                    int i = t + 256 * m;
                    u64 pv = __shfl_xor_sync(0xffffffffu, v[m], j);
                    v[m] = cmpsel(v[m], pv, i, k, j);
                }
            }
        }
    }

    if (t < KKEY) sidx[t] = (int)(~(unsigned int)v[0]);
    __syncthreads();

    // out shape (8, 64, 6) row-major; 3072 elements
#pragma unroll
    for (int o = t; o < 8 * KKEY * 6; o += 256) {
        int c = o % 6;
        int k = (o / 6) & (KKEY - 1);
        int b = o / (6 * KKEY);
        out[o] = src[(b * 6 + c) * N_PTS + sidx[k]];
    }
}

// ---------------------------------------------------------------------------
extern "C" void kernel_launch(void* const* d_in, const int* in_sizes, int n_in,
                              void* d_out, int out_size)
{
    const float* src = (const float*)d_in[0];   // src_pts (8,6,65536)
    // d_in[1] = tgt_pts (unused)
    const float* W1 = (const float*)d_in[2];
    const float* b1 = (const float*)d_in[3];
    const float* W2 = (const float*)d_in[4];
    const float* b2 = (const float*)d_in[5];
    const float* Wa = (const float*)d_in[6];
    const float* ba = (const float*)d_in[7];
    const float* Wb = (const float*)d_in[8];
    const float* bb = (const float*)d_in[9];
    const float* Wc = (const float*)d_in[10];
    const float* bc = (const float*)d_in[11];
    float* out = (float*)d_out;

    score_kernel<<<GRID_SCORE, NT>>>(
        src, W1, b1, W2, b2, Wa, ba, Wb, bb, Wc, bc);
    stage_kernel<<<16, 512>>>();
    final_kernel<<<1, 256>>>(src, out);
}

// round 11
// speedup vs baseline: 1.4298x; 1.1123x over previous
#include <cuda_runtime.h>
#include <math.h>

#define N_PTS 65536
#define KKEY 64
#define NT 512
#define GRID_SCORE 128   // 128 blocks x 512 threads = 65536 points, 1 pt/thread

typedef unsigned long long u64;

// scratch (no allocations allowed) — referenced ONLY from device code
__device__ u64 g_cand[GRID_SCORE * KKEY];   // 8192
__device__ u64 g_cand2[8 * KKEY];           // 512

// ---------------------------------------------------------------------------
// packed f32x2 helpers (FFMA2: 2 fp32 FMAs per instruction, only via PTX)
// ---------------------------------------------------------------------------
__device__ __forceinline__ u64 fma2(u64 a, u64 b, u64 c) {
    u64 d;
    asm("fma.rn.f32x2 %0, %1, %2, %3;" : "=l"(d) : "l"(a), "l"(b), "l"(c));
    return d;
}
__device__ __forceinline__ u64 add2(u64 a, u64 b) {
    u64 d;
    asm("add.rn.f32x2 %0, %1, %2;" : "=l"(d) : "l"(a), "l"(b));
    return d;
}
__device__ __forceinline__ u64 pack2(float lo, float hi) {
    u64 r;
    asm("mov.b64 %0, {%1, %2};" : "=l"(r) : "f"(lo), "f"(hi));
    return r;
}
__device__ __forceinline__ void unpack2(u64 x, float& lo, float& hi) {
    asm("mov.b64 {%0, %1}, %2;" : "=f"(lo), "=f"(hi) : "l"(x));
}
__device__ __forceinline__ u64 relu2(u64 x) {
    float lo, hi;
    unpack2(x, lo, hi);
    return pack2(fmaxf(lo, 0.0f), fmaxf(hi, 0.0f));
}

// ---------------------------------------------------------------------------
// bitonic compare-select, element at global position i, descending sort.
// Keys unique (low bits = ~index) so strict compare is fine.
// ---------------------------------------------------------------------------
__device__ __forceinline__ u64 cmpsel(u64 v, u64 pv, int i, int k, int j) {
    bool keep_max = (((i & k) == 0) == ((i & j) == 0));
    u64 mx = v > pv ? v : pv;
    u64 mn = v > pv ? pv : v;
    return keep_max ? mx : mn;
}

// ---------------------------------------------------------------------------
// Kernel 1: MLP score (batch 0), ONE point per thread; FFMA2 lanes carry two
// ADJACENT NEURONS (R10-proven math, verbatim). 512 threads/block so the
// in-block sort covers 512 keys -> only 64 blocks' worth of candidates.
// key = (bits(softplus) << 32) | ~n  (sp > 0 so bits are order-monotonic)
// ---------------------------------------------------------------------------
__global__ __launch_bounds__(NT) void score_kernel(
    const float* __restrict__ src,
    const float* __restrict__ W1, const float* __restrict__ b1,
    const float* __restrict__ W2, const float* __restrict__ b2,
    const float* __restrict__ Wa, const float* __restrict__ ba,
    const float* __restrict__ Wb, const float* __restrict__ bb_,
    const float* __restrict__ Wc, const float* __restrict__ bc)
{
    // neuron-paired weight layouts
    __shared__ __align__(16) u64 sW1p[96];     // [i<16][c<6] = (W1[2i,c], W1[2i+1,c])
    __shared__ __align__(16) u64 sW2p[1024];   // [j<64][i<16] = (W2[j,2i], W2[j,2i+1])
    __shared__ __align__(16) u64 sWaTp[512];   // [j<64][i<8] = (Wa[2i,j], Wa[2i+1,j])
    __shared__ __align__(16) u64 sWbp[64];     // [i<4][k<16] = (Wb[2i,k], Wb[2i+1,k])
    __shared__ __align__(16) u64 sWcp[4];      // [i<4] = (Wc[2i], Wc[2i+1])
    __shared__ u64 sb1p[16];                   // (b1[2i], b1[2i+1])
    __shared__ float sb2[64];
    __shared__ u64 sbap[8];
    __shared__ u64 sbbp[4];
    __shared__ float sbc;
    __shared__ u64 s_keys[NT];

    const int t = threadIdx.x;
    const int blk = blockIdx.x;

    // W2 rows are contiguous fp32 -> natural u64 pairs, direct copy
    for (int i = t; i < 1024; i += NT)
        sW2p[i] = ((const u64*)W2)[i];
    for (int idx = t; idx < 512; idx += NT) {
        int j = idx >> 3, i = idx & 7;
        sWaTp[idx] = pack2(Wa[(2 * i) * 64 + j], Wa[(2 * i + 1) * 64 + j]);
    }
    if (t < 96) {
        int i = t / 6, c = t % 6;
        sW1p[t] = pack2(W1[(2 * i) * 6 + c], W1[(2 * i + 1) * 6 + c]);
    }
    if (t >= 128 && t < 192) {
        int idx = t - 128;
        int i = idx >> 4, k = idx & 15;
        sWbp[idx] = pack2(Wb[(2 * i) * 16 + k], Wb[(2 * i + 1) * 16 + k]);
    }
    if (t >= 192 && t < 256) sb2[t - 192] = b2[t - 192];
    if (t >= 96 && t < 112)  sb1p[t - 96] = pack2(b1[2 * (t - 96)], b1[2 * (t - 96) + 1]);
    if (t >= 112 && t < 120) sbap[t - 112] = pack2(ba[2 * (t - 112)], ba[2 * (t - 112) + 1]);
    if (t >= 120 && t < 124) sbbp[t - 120] = pack2(bb_[2 * (t - 120)], bb_[2 * (t - 120) + 1]);
    if (t >= 124 && t < 128) sWcp[t - 124] = pack2(Wc[2 * (t - 124)], Wc[2 * (t - 124) + 1]);
    if (t == 0) sbc = bc[0];
    __syncthreads();

    const int n = blk * NT + t;   // point id

    u64 xd[6];
#pragma unroll
    for (int c = 0; c < 6; c++) {
        float xv = src[c * N_PTS + n];
        xd[c] = pack2(xv, xv);
    }

    // layer 1: 6 -> 32 (as 16 neuron-pairs), relu
    u64 h1p[16];
#pragma unroll
    for (int i = 0; i < 16; i++) {
        const ulonglong2* w = (const ulonglong2*)(sW1p + i * 6);
        ulonglong2 q0 = w[0], q1 = w[1], q2 = w[2];
        u64 v = sb1p[i];
        v = fma2(q0.x, xd[0], v);
        v = fma2(q0.y, xd[1], v);
        v = fma2(q1.x, xd[2], v);
        v = fma2(q1.y, xd[3], v);
        v = fma2(q2.x, xd[4], v);
        v = fma2(q2.y, xd[5], v);
        h1p[i] = relu2(v);
    }

    // layer 2 (32->64, relu) fused with layer a (64->16) accumulation
    u64 ap[8];
#pragma unroll
    for (int i = 0; i < 8; i++) ap[i] = sbap[i];

#pragma unroll 4
    for (int j = 0; j < 64; j++) {
        const ulonglong2* w2 = (const ulonglong2*)(sW2p + j * 16);
        u64 c0 = 0ULL, c1 = 0ULL, c2 = 0ULL, c3 = 0ULL;
#pragma unroll
        for (int i = 0; i < 16; i += 4) {
            ulonglong2 q0 = w2[i / 2];
            ulonglong2 q1 = w2[i / 2 + 1];
            c0 = fma2(q0.x, h1p[i],     c0);
            c1 = fma2(q0.y, h1p[i + 1], c1);
            c2 = fma2(q1.x, h1p[i + 2], c2);
            c3 = fma2(q1.y, h1p[i + 3], c3);
        }
        u64 s = add2(add2(c0, c1), add2(c2, c3));
        float lo, hi;
        unpack2(s, lo, hi);
        float v = fmaxf(sb2[j] + (lo + hi), 0.0f);
        u64 vd = pack2(v, v);

        const ulonglong2* wa = (const ulonglong2*)(sWaTp + j * 8);
#pragma unroll
        for (int i = 0; i < 8; i += 2) {
            ulonglong2 q = wa[i / 2];
            ap[i]     = fma2(q.x, vd, ap[i]);
            ap[i + 1] = fma2(q.y, vd, ap[i + 1]);
        }
    }
#pragma unroll
    for (int i = 0; i < 8; i++) ap[i] = relu2(ap[i]);

    // unpack a[16] and dup for layer b
    u64 afd[16];
#pragma unroll
    for (int i = 0; i < 8; i++) {
        float lo, hi;
        unpack2(ap[i], lo, hi);
        afd[2 * i]     = pack2(lo, lo);
        afd[2 * i + 1] = pack2(hi, hi);
    }

    // layer b: 16 -> 8 (as 4 neuron-pairs), relu
    u64 hbp[4];
#pragma unroll
    for (int i = 0; i < 4; i++) {
        const ulonglong2* wb = (const ulonglong2*)(sWbp + i * 16);
        u64 s0 = sbbp[i], s1 = 0ULL;
#pragma unroll
        for (int k = 0; k < 16; k += 4) {
            ulonglong2 q0 = wb[k / 2];
            ulonglong2 q1 = wb[k / 2 + 1];
            s0 = fma2(q0.x, afd[k],     s0);
            s1 = fma2(q0.y, afd[k + 1], s1);
            s0 = fma2(q1.x, afd[k + 2], s0);
            s1 = fma2(q1.y, afd[k + 3], s1);
        }
        hbp[i] = relu2(add2(s0, s1));
    }

    // layer c: 8 -> 1, softplus = max(x,0)+log1p(exp(-|x|))
    u64 cp = 0ULL;
#pragma unroll
    for (int i = 0; i < 4; i++) cp = fma2(sWcp[i], hbp[i], cp);
    float clo, chi;
    unpack2(cp, clo, chi);
    float c0f = sbc + (clo + chi);
    float sp = fmaxf(c0f, 0.0f) + log1pf(expf(-fabsf(c0f)));

    s_keys[t] = ((u64)__float_as_uint(sp) << 32) | (unsigned int)(~n);
    __syncthreads();

    // in-block selection: sort the block's 512 keys (descending), keep top-64
    {
        u64 v = s_keys[t];
#pragma unroll
        for (int k = 2; k <= 512; k <<= 1) {
#pragma unroll
            for (int j = k >> 1; j > 0; j >>= 1) {
                u64 v2;
                if (j >= 32) {
                    __syncthreads();
                    s_keys[t] = v;
                    __syncthreads();
                    v2 = s_keys[t ^ j];
                } else {
                    v2 = __shfl_xor_sync(0xffffffffu, v, j);
                }
                v = cmpsel(v, v2, t, k, j);
            }
        }
        if (t < KKEY) g_cand[blk * KKEY + t] = v;
    }
}

// ---------------------------------------------------------------------------
// Stage: 8 blocks, each sorts 1024 of the 8192 candidates (descending),
// emits its top-64 -> 512 survivors. 512 threads, 2 elems/thread.
// ---------------------------------------------------------------------------
__global__ __launch_bounds__(512) void stage_kernel()
{
    __shared__ u64 s[1024];
    const int t = threadIdx.x;
    const u64* p = g_cand + blockIdx.x * 1024;

    u64 v0 = p[t];
    u64 v1 = p[t + 512];

#pragma unroll
    for (int k = 2; k <= 1024; k <<= 1) {
#pragma unroll
        for (int j = k >> 1; j > 0; j >>= 1) {
            if (j >= 512) {
                bool keep_max = ((t & k) == 0);
                u64 mx = v0 > v1 ? v0 : v1;
                u64 mn = v0 > v1 ? v1 : v0;
                v0 = keep_max ? mx : mn;
                v1 = keep_max ? mn : mx;
            } else if (j >= 32) {
                __syncthreads();
                s[t] = v0;
                s[t + 512] = v1;
                __syncthreads();
                u64 p0 = s[t ^ j];
                u64 p1 = s[(t + 512) ^ j];
                v0 = cmpsel(v0, p0, t, k, j);
                v1 = cmpsel(v1, p1, t + 512, k, j);
            } else {
                u64 p0 = __shfl_xor_sync(0xffffffffu, v0, j);
                u64 p1 = __shfl_xor_sync(0xffffffffu, v1, j);
                v0 = cmpsel(v0, p0, t, k, j);
                v1 = cmpsel(v1, p1, t + 512, k, j);
            }
        }
    }

    if (t < KKEY) g_cand2[blockIdx.x * KKEY + t] = v0;
}

// ---------------------------------------------------------------------------
// Final: 1 block, 256 threads: sort the 512 survivors (2 elems/thread),
// take top-64 indices, fused gather: out[b,k,c] = src_pts[b,c,idx[k]]
// ---------------------------------------------------------------------------
__global__ __launch_bounds__(256) void final_kernel(
    const float* __restrict__ src, float* __restrict__ out)
{
    __shared__ u64 s[512];
    __shared__ int sidx[KKEY];
    const int t = threadIdx.x;

    u64 v0 = g_cand2[t];
    u64 v1 = g_cand2[t + 256];

#pragma unroll
    for (int k = 2; k <= 512; k <<= 1) {
#pragma unroll
        for (int j = k >> 1; j > 0; j >>= 1) {
            if (j >= 256) {
                bool keep_max = ((t & k) == 0);
                u64 mx = v0 > v1 ? v0 : v1;
                u64 mn = v0 > v1 ? v1 : v0;
                v0 = keep_max ? mx : mn;
                v1 = keep_max ? mn : mx;
            } else if (j >= 32) {
                __syncthreads();
                s[t] = v0;
                s[t + 256] = v1;
                __syncthreads();
                u64 p0 = s[t ^ j];
                u64 p1 = s[(t + 256) ^ j];
                v0 = cmpsel(v0, p0, t, k, j);
                v1 = cmpsel(v1, p1, t + 256, k, j);
            } else {
                u64 p0 = __shfl_xor_sync(0xffffffffu, v0, j);
                u64 p1 = __shfl_xor_sync(0xffffffffu, v1, j);
                v0 = cmpsel(v0, p0, t, k, j);
                v1 = cmpsel(v1, p1, t + 256, k, j);
            }
        }
    }

    if (t < KKEY) sidx[t] = (int)(~(unsigned int)v0);
    __syncthreads();

    // out shape (8, 64, 6) row-major; 3072 elements
#pragma unroll
    for (int o = t; o < 8 * KKEY * 6; o += 256) {
        int c = o % 6;
        int k = (o / 6) & (KKEY - 1);
        int b = o / (6 * KKEY);
        out[o] = src[(b * 6 + c) * N_PTS + sidx[k]];
    }
}

// ---------------------------------------------------------------------------
extern "C" void kernel_launch(void* const* d_in, const int* in_sizes, int n_in,
                              void* d_out, int out_size)
{
    const float* src = (const float*)d_in[0];   // src_pts (8,6,65536)
    // d_in[1] = tgt_pts (unused)
    const float* W1 = (const float*)d_in[2];
    const float* b1 = (const float*)d_in[3];
    const float* W2 = (const float*)d_in[4];
    const float* b2 = (const float*)d_in[5];
    const float* Wa = (const float*)d_in[6];
    const float* ba = (const float*)d_in[7];
    const float* Wb = (const float*)d_in[8];
    const float* bb = (const float*)d_in[9];
    const float* Wc = (const float*)d_in[10];
    const float* bc = (const float*)d_in[11];
    float* out = (float*)d_out;

    score_kernel<<<GRID_SCORE, NT>>>(
        src, W1, b1, W2, b2, Wa, ba, Wb, bb, Wc, bc);
    stage_kernel<<<8, 512>>>();
    final_kernel<<<1, 256>>>(src, out);
}

// round 12
// speedup vs baseline: 1.5108x; 1.0567x over previous
#include <cuda_runtime.h>
#include <math.h>

#define N_PTS 65536
#define KKEY 64
#define NT 512
#define GRID_SCORE 128   // 128 blocks x 512 threads = 65536 points, 1 pt/thread

typedef unsigned long long u64;

// scratch (no allocations allowed) — referenced ONLY from device code
__device__ u64 g_cand[GRID_SCORE * KKEY];   // 8192
__device__ u64 g_cand2[8 * KKEY];           // 512
__device__ unsigned g_done;                  // zero-init; reset by elected block

// ---------------------------------------------------------------------------
// packed f32x2 helpers (FFMA2: 2 fp32 FMAs per instruction, only via PTX)
// ---------------------------------------------------------------------------
__device__ __forceinline__ u64 fma2(u64 a, u64 b, u64 c) {
    u64 d;
    asm("fma.rn.f32x2 %0, %1, %2, %3;" : "=l"(d) : "l"(a), "l"(b), "l"(c));
    return d;
}
__device__ __forceinline__ u64 add2(u64 a, u64 b) {
    u64 d;
    asm("add.rn.f32x2 %0, %1, %2;" : "=l"(d) : "l"(a), "l"(b));
    return d;
}
__device__ __forceinline__ u64 pack2(float lo, float hi) {
    u64 r;
    asm("mov.b64 %0, {%1, %2};" : "=l"(r) : "f"(lo), "f"(hi));
    return r;
}
__device__ __forceinline__ void unpack2(u64 x, float& lo, float& hi) {
    asm("mov.b64 {%0, %1}, %2;" : "=f"(lo), "=f"(hi) : "l"(x));
}
__device__ __forceinline__ u64 relu2(u64 x) {
    float lo, hi;
    unpack2(x, lo, hi);
    return pack2(fmaxf(lo, 0.0f), fmaxf(hi, 0.0f));
}

// ---------------------------------------------------------------------------
// bitonic compare-select, element at global position i, descending sort.
// Keys unique (low bits = ~index) so strict compare is fine.
// ---------------------------------------------------------------------------
__device__ __forceinline__ u64 cmpsel(u64 v, u64 pv, int i, int k, int j) {
    bool keep_max = (((i & k) == 0) == ((i & j) == 0));
    u64 mx = v > pv ? v : pv;
    u64 mn = v > pv ? pv : v;
    return keep_max ? mx : mn;
}

// ---------------------------------------------------------------------------
// Kernel 1: MLP score (batch 0), ONE point per thread.
// Layer 1 / b / c: FFMA2 lanes = two adjacent NEURONS (R10/R11-proven).
// Layer 2+a: FFMA2 lanes = two adjacent J-OUTPUTS (j-pairing) — removes the
// per-j serial horizontal chain. Then in-block sort-512 -> block top-64.
// key = (bits(softplus) << 32) | ~n  (sp > 0 so bits are order-monotonic)
// ---------------------------------------------------------------------------
__global__ __launch_bounds__(NT) void score_kernel(
    const float* __restrict__ src,
    const float* __restrict__ W1, const float* __restrict__ b1,
    const float* __restrict__ W2, const float* __restrict__ b2,
    const float* __restrict__ Wa, const float* __restrict__ ba,
    const float* __restrict__ Wb, const float* __restrict__ bb_,
    const float* __restrict__ Wc, const float* __restrict__ bc)
{
    __shared__ __align__(16) u64 sW1p[96];     // [i<16][c<6] = (W1[2i,c], W1[2i+1,c])
    __shared__ __align__(16) u64 sW2p[1024];   // [j<64][i<16] = (W2[j,2i], W2[j,2i+1])
    __shared__ __align__(16) u64 sWaJp[512];   // [jp<32][i<16] = (Wa[i,2jp], Wa[i,2jp+1])
    __shared__ __align__(16) u64 sWbp[64];     // [i<4][k<16] = (Wb[2i,k], Wb[2i+1,k])
    __shared__ __align__(16) u64 sWcp[4];      // (Wc[2i], Wc[2i+1])
    __shared__ u64 sb1p[16];                   // (b1[2i], b1[2i+1])
    __shared__ u64 sb2p[32];                   // (b2[2jp], b2[2jp+1])
    __shared__ float sba[16];
    __shared__ u64 sbbp[4];
    __shared__ float sbc;
    __shared__ u64 s_keys[NT];

    const int t = threadIdx.x;
    const int blk = blockIdx.x;

    // W2 rows are contiguous fp32 -> natural u64 pairs, direct copy
    for (int i = t; i < 1024; i += NT)
        sW2p[i] = ((const u64*)W2)[i];
    for (int idx = t; idx < 512; idx += NT) {
        int jp = idx >> 4, i = idx & 15;
        sWaJp[idx] = pack2(Wa[i * 64 + 2 * jp], Wa[i * 64 + 2 * jp + 1]);
    }
    if (t < 96) {
        int i = t / 6, c = t % 6;
        sW1p[t] = pack2(W1[(2 * i) * 6 + c], W1[(2 * i + 1) * 6 + c]);
    }
    if (t >= 96 && t < 112)  sb1p[t - 96] = pack2(b1[2 * (t - 96)], b1[2 * (t - 96) + 1]);
    if (t >= 112 && t < 128) sba[t - 112] = ba[t - 112];
    if (t >= 128 && t < 192) {
        int idx = t - 128;
        int i = idx >> 4, k = idx & 15;
        sWbp[idx] = pack2(Wb[(2 * i) * 16 + k], Wb[(2 * i + 1) * 16 + k]);
    }
    if (t >= 192 && t < 224) sb2p[t - 192] = ((const u64*)b2)[t - 192];
    if (t >= 224 && t < 228) sbbp[t - 224] = pack2(bb_[2 * (t - 224)], bb_[2 * (t - 224) + 1]);
    if (t >= 228 && t < 232) sWcp[t - 228] = pack2(Wc[2 * (t - 228)], Wc[2 * (t - 228) + 1]);
    if (t == 0) sbc = bc[0];
    __syncthreads();

    const int n = blk * NT + t;   // point id

    u64 xd[6];
#pragma unroll
    for (int c = 0; c < 6; c++) {
        float xv = src[c * N_PTS + n];
        xd[c] = pack2(xv, xv);
    }

    // layer 1: 6 -> 32 (as 16 neuron-pairs), relu
    u64 h1p[16];
#pragma unroll
    for (int i = 0; i < 16; i++) {
        const ulonglong2* w = (const ulonglong2*)(sW1p + i * 6);
        ulonglong2 q0 = w[0], q1 = w[1], q2 = w[2];
        u64 v = sb1p[i];
        v = fma2(q0.x, xd[0], v);
        v = fma2(q0.y, xd[1], v);
        v = fma2(q1.x, xd[2], v);
        v = fma2(q1.y, xd[3], v);
        v = fma2(q2.x, xd[4], v);
        v = fma2(q2.y, xd[5], v);
        h1p[i] = relu2(v);
    }

    // layer 2 (32->64, relu) fused with layer a (64->16): j-paired.
    // ap[i] lanes = (ba[i] + sum over even j, sum over odd j)
    u64 ap[16];
#pragma unroll
    for (int i = 0; i < 16; i++) ap[i] = pack2(sba[i], 0.0f);

#pragma unroll 2
    for (int jp = 0; jp < 32; jp++) {
        const ulonglong2* w2 = (const ulonglong2*)(sW2p + (2 * jp) * 16);
        u64 cA0 = 0ULL, cA1 = 0ULL, cB0 = 0ULL, cB1 = 0ULL;
#pragma unroll
        for (int i = 0; i < 16; i += 4) {
            ulonglong2 qa0 = w2[i / 2];
            ulonglong2 qa1 = w2[i / 2 + 1];
            ulonglong2 qb0 = w2[8 + i / 2];
            ulonglong2 qb1 = w2[8 + i / 2 + 1];
            cA0 = fma2(qa0.x, h1p[i],     cA0);
            cA1 = fma2(qa0.y, h1p[i + 1], cA1);
            cA0 = fma2(qa1.x, h1p[i + 2], cA0);
            cA1 = fma2(qa1.y, h1p[i + 3], cA1);
            cB0 = fma2(qb0.x, h1p[i],     cB0);
            cB1 = fma2(qb0.y, h1p[i + 1], cB1);
            cB0 = fma2(qb1.x, h1p[i + 2], cB0);
            cB1 = fma2(qb1.y, h1p[i + 3], cB1);
        }
        u64 sA = add2(cA0, cA1);
        u64 sB = add2(cB0, cB1);
        float alo, ahi, blo, bhi;
        unpack2(sA, alo, ahi);
        unpack2(sB, blo, bhi);
        // lanes -> (sum_j0, sum_j1), then + (b2[j0], b2[j1]), lanewise relu
        u64 sum = add2(add2(pack2(alo, blo), pack2(ahi, bhi)), sb2p[jp]);
        float v0f, v1f;
        unpack2(sum, v0f, v1f);
        u64 vd = pack2(fmaxf(v0f, 0.0f), fmaxf(v1f, 0.0f));

        const ulonglong2* wa = (const ulonglong2*)(sWaJp + jp * 16);
#pragma unroll
        for (int i = 0; i < 16; i += 2) {
            ulonglong2 q = wa[i / 2];
            ap[i]     = fma2(q.x, vd, ap[i]);
            ap[i + 1] = fma2(q.y, vd, ap[i + 1]);
        }
    }

    // horizontalize layer-a accumulators once; relu; dup for layer b
    u64 afd[16];
#pragma unroll
    for (int i = 0; i < 16; i++) {
        float lo, hi;
        unpack2(ap[i], lo, hi);
        float av = fmaxf(lo + hi, 0.0f);
        afd[i] = pack2(av, av);
    }

    // layer b: 16 -> 8 (as 4 neuron-pairs), relu
    u64 hbp[4];
#pragma unroll
    for (int i = 0; i < 4; i++) {
        const ulonglong2* wb = (const ulonglong2*)(sWbp + i * 16);
        u64 s0 = sbbp[i], s1 = 0ULL;
#pragma unroll
        for (int k = 0; k < 16; k += 4) {
            ulonglong2 q0 = wb[k / 2];
            ulonglong2 q1 = wb[k / 2 + 1];
            s0 = fma2(q0.x, afd[k],     s0);
            s1 = fma2(q0.y, afd[k + 1], s1);
            s0 = fma2(q1.x, afd[k + 2], s0);
            s1 = fma2(q1.y, afd[k + 3], s1);
        }
        hbp[i] = relu2(add2(s0, s1));
    }

    // layer c: 8 -> 1, softplus = max(x,0)+log1p(exp(-|x|))
    u64 cp = 0ULL;
#pragma unroll
    for (int i = 0; i < 4; i++) cp = fma2(sWcp[i], hbp[i], cp);
    float clo, chi;
    unpack2(cp, clo, chi);
    float c0f = sbc + (clo + chi);
    float sp = fmaxf(c0f, 0.0f) + log1pf(expf(-fabsf(c0f)));

    s_keys[t] = ((u64)__float_as_uint(sp) << 32) | (unsigned int)(~n);
    __syncthreads();

    // in-block selection: sort the block's 512 keys (descending), keep top-64
    {
        u64 v = s_keys[t];
#pragma unroll
        for (int k = 2; k <= 512; k <<= 1) {
#pragma unroll
            for (int j = k >> 1; j > 0; j >>= 1) {
                u64 v2;
                if (j >= 32) {
                    __syncthreads();
                    s_keys[t] = v;
                    __syncthreads();
                    v2 = s_keys[t ^ j];
                } else {
                    v2 = __shfl_xor_sync(0xffffffffu, v, j);
                }
                v = cmpsel(v, v2, t, k, j);
            }
        }
        if (t < KKEY) g_cand[blk * KKEY + t] = v;
    }
}

// ---------------------------------------------------------------------------
// Merged tail: 8 blocks. Each sorts 1024 of the 8192 candidates -> top-64
// into g_cand2. The LAST finisher (atomic election; output independent of
// which block wins) sorts the 512 survivors and does the fused gather.
// ---------------------------------------------------------------------------
__global__ __launch_bounds__(512) void tail_kernel(
    const float* __restrict__ src, float* __restrict__ out)
{
    __shared__ u64 s[1024];
    __shared__ int sidx[KKEY];
    __shared__ unsigned s_old;
    const int t = threadIdx.x;
    const u64* p = g_cand + blockIdx.x * 1024;

    // ---- phase A: sort my 1024 chunk (descending), emit top-64 ----
    u64 v0 = p[t];
    u64 v1 = p[t + 512];

#pragma unroll
    for (int k = 2; k <= 1024; k <<= 1) {
#pragma unroll
        for (int j = k >> 1; j > 0; j >>= 1) {
            if (j >= 512) {
                bool keep_max = ((t & k) == 0);
                u64 mx = v0 > v1 ? v0 : v1;
                u64 mn = v0 > v1 ? v1 : v0;
                v0 = keep_max ? mx : mn;
                v1 = keep_max ? mn : mx;
            } else if (j >= 32) {
                __syncthreads();
                s[t] = v0;
                s[t + 512] = v1;
                __syncthreads();
                u64 p0 = s[t ^ j];
                u64 p1 = s[(t + 512) ^ j];
                v0 = cmpsel(v0, p0, t, k, j);
                v1 = cmpsel(v1, p1, t + 512, k, j);
            } else {
                u64 p0 = __shfl_xor_sync(0xffffffffu, v0, j);
                u64 p1 = __shfl_xor_sync(0xffffffffu, v1, j);
                v0 = cmpsel(v0, p0, t, k, j);
                v1 = cmpsel(v1, p1, t + 512, k, j);
            }
        }
    }
    if (t < KKEY) g_cand2[blockIdx.x * KKEY + t] = v0;

    // ---- election: last block to finish proceeds to phase B ----
    __threadfence();
    __syncthreads();
    if (t == 0) s_old = atomicAdd(&g_done, 1u);
    __syncthreads();
    if (s_old != 7u) return;
    __threadfence();

    // ---- phase B: sort the 512 survivors (1 elem/thread), top-64 + gather ----
    {
        u64 v = g_cand2[t];
#pragma unroll
        for (int k = 2; k <= 512; k <<= 1) {
#pragma unroll
            for (int j = k >> 1; j > 0; j >>= 1) {
                u64 v2;
                if (j >= 32) {
                    __syncthreads();
                    s[t] = v;
                    __syncthreads();
                    v2 = s[t ^ j];
                } else {
                    v2 = __shfl_xor_sync(0xffffffffu, v, j);
                }
                v = cmpsel(v, v2, t, k, j);
            }
        }
        if (t < KKEY) sidx[t] = (int)(~(unsigned int)v);
        __syncthreads();

        // out shape (8, 64, 6) row-major; 3072 elements
#pragma unroll
        for (int o = t; o < 8 * KKEY * 6; o += 512) {
            int c = o % 6;
            int k = (o / 6) & (KKEY - 1);
            int b = o / (6 * KKEY);
            out[o] = src[(b * 6 + c) * N_PTS + sidx[k]];
        }

        __syncthreads();
        if (t == 0) g_done = 0u;   // reset for graph replay; elected block is last
    }
}

// ---------------------------------------------------------------------------
extern "C" void kernel_launch(void* const* d_in, const int* in_sizes, int n_in,
                              void* d_out, int out_size)
{
    const float* src = (const float*)d_in[0];   // src_pts (8,6,65536)
    // d_in[1] = tgt_pts (unused)
    const float* W1 = (const float*)d_in[2];
    const float* b1 = (const float*)d_in[3];
    const float* W2 = (const float*)d_in[4];
    const float* b2 = (const float*)d_in[5];
    const float* Wa = (const float*)d_in[6];
    const float* ba = (const float*)d_in[7];
    const float* Wb = (const float*)d_in[8];
    const float* bb = (const float*)d_in[9];
    const float* Wc = (const float*)d_in[10];
    const float* bc = (const float*)d_in[11];
    float* out = (float*)d_out;

    score_kernel<<<GRID_SCORE, NT>>>(
        src, W1, b1, W2, b2, Wa, ba, Wb, bb, Wc, bc);
    tail_kernel<<<8, 512>>>(src, out);
}

// round 13
// speedup vs baseline: 1.8462x; 1.2220x over previous
#include <cuda_runtime.h>
#include <math.h>

#define N_PTS 65536
#define KKEY 64
#define NT 512
#define GRID_SCORE 128   // 128 blocks x 512 threads = 65536 points, 1 pt/thread

typedef unsigned long long u64;

// scratch (no allocations allowed) — referenced ONLY from device code
__device__ u64 g_cand[GRID_SCORE * KKEY];   // 8192 (128 sorted-64 lists)
__device__ u64 g_cand2[8 * KKEY];           // 512  (8 sorted-64 lists)
__device__ unsigned g_done;                  // zero-init; reset by elected block

// ---------------------------------------------------------------------------
// packed f32x2 helpers (FFMA2: 2 fp32 FMAs per instruction, only via PTX)
// ---------------------------------------------------------------------------
__device__ __forceinline__ u64 fma2(u64 a, u64 b, u64 c) {
    u64 d;
    asm("fma.rn.f32x2 %0, %1, %2, %3;" : "=l"(d) : "l"(a), "l"(b), "l"(c));
    return d;
}
__device__ __forceinline__ u64 add2(u64 a, u64 b) {
    u64 d;
    asm("add.rn.f32x2 %0, %1, %2;" : "=l"(d) : "l"(a), "l"(b));
    return d;
}
__device__ __forceinline__ u64 pack2(float lo, float hi) {
    u64 r;
    asm("mov.b64 %0, {%1, %2};" : "=l"(r) : "f"(lo), "f"(hi));
    return r;
}
__device__ __forceinline__ void unpack2(u64 x, float& lo, float& hi) {
    asm("mov.b64 {%0, %1}, %2;" : "=f"(lo), "=f"(hi) : "l"(x));
}
__device__ __forceinline__ u64 relu2(u64 x) {
    float lo, hi;
    unpack2(x, lo, hi);
    return pack2(fmaxf(lo, 0.0f), fmaxf(hi, 0.0f));
}

// ---------------------------------------------------------------------------
// bitonic compare-select, element at global position i, descending sort.
// Keys unique (low bits = ~index) so strict compare is fine.
// ---------------------------------------------------------------------------
__device__ __forceinline__ u64 cmpsel(u64 v, u64 pv, int i, int k, int j) {
    bool keep_max = (((i & k) == 0) == ((i & j) == 0));
    u64 mx = v > pv ? v : pv;
    u64 mn = v > pv ? pv : v;
    return keep_max ? mx : mn;
}

// ---------------------------------------------------------------------------
// warp-local sort of 64 elements (v0 = pos lane, v1 = pos lane+32),
// descending, barrier-free (shfl only; j==32 is in-thread).
// ---------------------------------------------------------------------------
__device__ __forceinline__ void warp_sort64(u64& v0, u64& v1, int lane) {
#pragma unroll
    for (int k = 2; k <= 64; k <<= 1) {
#pragma unroll
        for (int j = k >> 1; j > 0; j >>= 1) {
            if (j == 32) {
                // pair (lane, lane+32); direction from (lane & k)
                bool dirdesc = ((lane & k) == 0);
                u64 mx = v0 > v1 ? v0 : v1;
                u64 mn = v0 > v1 ? v1 : v0;
                v0 = dirdesc ? mx : mn;
                v1 = dirdesc ? mn : mx;
            } else {
                u64 p0 = __shfl_xor_sync(0xffffffffu, v0, j);
                u64 p1 = __shfl_xor_sync(0xffffffffu, v1, j);
                v0 = cmpsel(v0, p0, lane, k, j);
                v1 = cmpsel(v1, p1, lane + 32, k, j);
            }
        }
    }
}

// ---------------------------------------------------------------------------
// merge two sorted-descending 64-lists, keeping the sorted top-64 in (a0,a1).
// w[i] = max(A[i], B[63-i]) is bitonic and contains the top-64; then a
// 6-substage descending bitonic merge. Barrier-free.
// ---------------------------------------------------------------------------
__device__ __forceinline__ void warp_merge64(u64& a0, u64& a1, u64 b0, u64 b1,
                                             int lane) {
    u64 rb1 = __shfl_sync(0xffffffffu, b1, 31 - lane);  // B[63-lane]
    u64 rb0 = __shfl_sync(0xffffffffu, b0, 31 - lane);  // B[63-(lane+32)]
    u64 w0 = a0 > rb1 ? a0 : rb1;
    u64 w1 = a1 > rb0 ? a1 : rb0;
    // bitonic merge, descending: j=32 in-thread, then 16..1 via shfl
    {
        u64 mx = w0 > w1 ? w0 : w1;
        u64 mn = w0 > w1 ? w1 : w0;
        w0 = mx; w1 = mn;
    }
#pragma unroll
    for (int j = 16; j > 0; j >>= 1) {
        u64 p0 = __shfl_xor_sync(0xffffffffu, w0, j);
        u64 p1 = __shfl_xor_sync(0xffffffffu, w1, j);
        bool low = ((lane & j) == 0);
        w0 = low ? (w0 > p0 ? w0 : p0) : (w0 < p0 ? w0 : p0);
        w1 = low ? (w1 > p1 ? w1 : p1) : (w1 < p1 ? w1 : p1);
    }
    a0 = w0; a1 = w1;
}

// ---------------------------------------------------------------------------
// Kernel 1: MLP score (batch 0), ONE point per thread (R12-proven math:
// layer1/b/c neuron-paired FFMA2; layer2+a j-paired FFMA2). Selection:
// warps 0..7 warp-sort-64 their chunk, then 3 merge levels -> sorted top-64.
// key = (bits(softplus) << 32) | ~n  (sp > 0 so bits are order-monotonic)
// ---------------------------------------------------------------------------
__global__ __launch_bounds__(NT) void score_kernel(
    const float* __restrict__ src,
    const float* __restrict__ W1, const float* __restrict__ b1,
    const float* __restrict__ W2, const float* __restrict__ b2,
    const float* __restrict__ Wa, const float* __restrict__ ba,
    const float* __restrict__ Wb, const float* __restrict__ bb_,
    const float* __restrict__ Wc, const float* __restrict__ bc)
{
    __shared__ __align__(16) u64 sW1p[96];     // [i<16][c<6] = (W1[2i,c], W1[2i+1,c])
    __shared__ __align__(16) u64 sW2p[1024];   // [j<64][i<16] = (W2[j,2i], W2[j,2i+1])
    __shared__ __align__(16) u64 sWaJp[512];   // [jp<32][i<16] = (Wa[i,2jp], Wa[i,2jp+1])
    __shared__ __align__(16) u64 sWbp[64];     // [i<4][k<16] = (Wb[2i,k], Wb[2i+1,k])
    __shared__ __align__(16) u64 sWcp[4];      // (Wc[2i], Wc[2i+1])
    __shared__ u64 sb1p[16];                   // (b1[2i], b1[2i+1])
    __shared__ u64 sb2p[32];                   // (b2[2jp], b2[2jp+1])
    __shared__ float sba[16];
    __shared__ u64 sbbp[4];
    __shared__ float sbc;
    __shared__ u64 s_keys[NT];

    const int t = threadIdx.x;
    const int blk = blockIdx.x;
    const int lane = t & 31;
    const int w = t >> 5;

    // W2 rows are contiguous fp32 -> natural u64 pairs, direct copy
    for (int i = t; i < 1024; i += NT)
        sW2p[i] = ((const u64*)W2)[i];
    for (int idx = t; idx < 512; idx += NT) {
        int jp = idx >> 4, i = idx & 15;
        sWaJp[idx] = pack2(Wa[i * 64 + 2 * jp], Wa[i * 64 + 2 * jp + 1]);
    }
    if (t < 96) {
        int i = t / 6, c = t % 6;
        sW1p[t] = pack2(W1[(2 * i) * 6 + c], W1[(2 * i + 1) * 6 + c]);
    }
    if (t >= 96 && t < 112)  sb1p[t - 96] = pack2(b1[2 * (t - 96)], b1[2 * (t - 96) + 1]);
    if (t >= 112 && t < 128) sba[t - 112] = ba[t - 112];
    if (t >= 128 && t < 192) {
        int idx = t - 128;
        int i = idx >> 4, k = idx & 15;
        sWbp[idx] = pack2(Wb[(2 * i) * 16 + k], Wb[(2 * i + 1) * 16 + k]);
    }
    if (t >= 192 && t < 224) sb2p[t - 192] = ((const u64*)b2)[t - 192];
    if (t >= 224 && t < 228) sbbp[t - 224] = pack2(bb_[2 * (t - 224)], bb_[2 * (t - 224) + 1]);
    if (t >= 228 && t < 232) sWcp[t - 228] = pack2(Wc[2 * (t - 228)], Wc[2 * (t - 228) + 1]);
    if (t == 0) sbc = bc[0];
    __syncthreads();

    const int n = blk * NT + t;   // point id

    u64 xd[6];
#pragma unroll
    for (int c = 0; c < 6; c++) {
        float xv = src[c * N_PTS + n];
        xd[c] = pack2(xv, xv);
    }

    // layer 1: 6 -> 32 (as 16 neuron-pairs), relu
    u64 h1p[16];
#pragma unroll
    for (int i = 0; i < 16; i++) {
        const ulonglong2* wq = (const ulonglong2*)(sW1p + i * 6);
        ulonglong2 q0 = wq[0], q1 = wq[1], q2 = wq[2];
        u64 v = sb1p[i];
        v = fma2(q0.x, xd[0], v);
        v = fma2(q0.y, xd[1], v);
        v = fma2(q1.x, xd[2], v);
        v = fma2(q1.y, xd[3], v);
        v = fma2(q2.x, xd[4], v);
        v = fma2(q2.y, xd[5], v);
        h1p[i] = relu2(v);
    }

    // layer 2 (32->64, relu) fused with layer a (64->16): j-paired
    u64 ap[16];
#pragma unroll
    for (int i = 0; i < 16; i++) ap[i] = pack2(sba[i], 0.0f);

#pragma unroll 2
    for (int jp = 0; jp < 32; jp++) {
        const ulonglong2* w2 = (const ulonglong2*)(sW2p + (2 * jp) * 16);
        u64 cA0 = 0ULL, cA1 = 0ULL, cB0 = 0ULL, cB1 = 0ULL;
#pragma unroll
        for (int i = 0; i < 16; i += 4) {
            ulonglong2 qa0 = w2[i / 2];
            ulonglong2 qa1 = w2[i / 2 + 1];
            ulonglong2 qb0 = w2[8 + i / 2];
            ulonglong2 qb1 = w2[8 + i / 2 + 1];
            cA0 = fma2(qa0.x, h1p[i],     cA0);
            cA1 = fma2(qa0.y, h1p[i + 1], cA1);
            cA0 = fma2(qa1.x, h1p[i + 2], cA0);
            cA1 = fma2(qa1.y, h1p[i + 3], cA1);
            cB0 = fma2(qb0.x, h1p[i],     cB0);
            cB1 = fma2(qb0.y, h1p[i + 1], cB1);
            cB0 = fma2(qb1.x, h1p[i + 2], cB0);
            cB1 = fma2(qb1.y, h1p[i + 3], cB1);
        }
        u64 sA = add2(cA0, cA1);
        u64 sB = add2(cB0, cB1);
        float alo, ahi, blo, bhi;
        unpack2(sA, alo, ahi);
        unpack2(sB, blo, bhi);
        u64 sum = add2(add2(pack2(alo, blo), pack2(ahi, bhi)), sb2p[jp]);
        float v0f, v1f;
        unpack2(sum, v0f, v1f);
        u64 vd = pack2(fmaxf(v0f, 0.0f), fmaxf(v1f, 0.0f));

        const ulonglong2* wa = (const ulonglong2*)(sWaJp + jp * 16);
#pragma unroll
        for (int i = 0; i < 16; i += 2) {
            ulonglong2 q = wa[i / 2];
            ap[i]     = fma2(q.x, vd, ap[i]);
            ap[i + 1] = fma2(q.y, vd, ap[i + 1]);
        }
    }

    // horizontalize layer-a accumulators; relu; dup for layer b
    u64 afd[16];
#pragma unroll
    for (int i = 0; i < 16; i++) {
        float lo, hi;
        unpack2(ap[i], lo, hi);
        float av = fmaxf(lo + hi, 0.0f);
        afd[i] = pack2(av, av);
    }

    // layer b: 16 -> 8 (as 4 neuron-pairs), relu
    u64 hbp[4];
#pragma unroll
    for (int i = 0; i < 4; i++) {
        const ulonglong2* wb = (const ulonglong2*)(sWbp + i * 16);
        u64 s0 = sbbp[i], s1 = 0ULL;
#pragma unroll
        for (int k = 0; k < 16; k += 4) {
            ulonglong2 q0 = wb[k / 2];
            ulonglong2 q1 = wb[k / 2 + 1];
            s0 = fma2(q0.x, afd[k],     s0);
            s1 = fma2(q0.y, afd[k + 1], s1);
            s0 = fma2(q1.x, afd[k + 2], s0);
            s1 = fma2(q1.y, afd[k + 3], s1);
        }
        hbp[i] = relu2(add2(s0, s1));
    }

    // layer c: 8 -> 1, softplus = max(x,0)+log1p(exp(-|x|))
    u64 cp = 0ULL;
#pragma unroll
    for (int i = 0; i < 4; i++) cp = fma2(sWcp[i], hbp[i], cp);
    float clo, chi;
    unpack2(cp, clo, chi);
    float c0f = sbc + (clo + chi);
    float sp = fmaxf(c0f, 0.0f) + log1pf(expf(-fabsf(c0f)));

    s_keys[t] = ((u64)__float_as_uint(sp) << 32) | (unsigned int)(~n);
    __syncthreads();

    // selection: warps 0..7 sort 64-chunks, then 3 merge levels -> top-64
    {
        u64 v0 = 0ULL, v1 = 0ULL;
        if (w < 8) {
            v0 = s_keys[w * 64 + lane];
            v1 = s_keys[w * 64 + 32 + lane];
            warp_sort64(v0, v1, lane);
        }
        for (int nl = 8; nl > 1; nl >>= 1) {
            int half = nl >> 1;
            __syncthreads();
            if (w >= half && w < nl) {
                s_keys[(w - half) * 64 + lane] = v0;
                s_keys[(w - half) * 64 + 32 + lane] = v1;
            }
            __syncthreads();
            if (w < half) {
                u64 b0 = s_keys[w * 64 + lane];
                u64 b1 = s_keys[w * 64 + 32 + lane];
                warp_merge64(v0, v1, b0, b1, lane);
            }
        }
        if (w == 0) {
            g_cand[blk * KKEY + lane] = v0;
            g_cand[blk * KKEY + 32 + lane] = v1;
        }
    }
}

// ---------------------------------------------------------------------------
// Tail: 8 blocks x 512 threads. Phase A: each warp owns one of the block's
// 16 sorted-64 lists; 4 merge levels -> block top-64 into g_cand2. Last
// finisher (atomic election) merges the 8 block lists (3 levels) + gather.
// ---------------------------------------------------------------------------
__global__ __launch_bounds__(512) void tail_kernel(
    const float* __restrict__ src, float* __restrict__ out)
{
    __shared__ u64 sx[512];
    __shared__ int sidx[KKEY];
    __shared__ unsigned s_old;
    const int t = threadIdx.x;
    const int lane = t & 31;
    const int w = t >> 5;

    // phase A: merge this block's 16 sorted lists
    u64 v0 = g_cand[(blockIdx.x * 16 + w) * KKEY + lane];
    u64 v1 = g_cand[(blockIdx.x * 16 + w) * KKEY + 32 + lane];

    for (int nl = 16; nl > 1; nl >>= 1) {
        int half = nl >> 1;
        __syncthreads();
        if (w >= half && w < nl) {
            sx[(w - half) * 64 + lane] = v0;
            sx[(w - half) * 64 + 32 + lane] = v1;
        }
        __syncthreads();
        if (w < half) {
            u64 b0 = sx[w * 64 + lane];
            u64 b1 = sx[w * 64 + 32 + lane];
            warp_merge64(v0, v1, b0, b1, lane);
        }
    }
    if (w == 0) {
        g_cand2[blockIdx.x * KKEY + lane] = v0;
        g_cand2[blockIdx.x * KKEY + 32 + lane] = v1;
    }

    // election: last block to finish proceeds
    __threadfence();
    __syncthreads();
    if (t == 0) s_old = atomicAdd(&g_done, 1u);
    __syncthreads();
    if (s_old != 7u) return;
    __threadfence();

    // phase B: merge the 8 block lists -> global sorted top-64
    if (w < 8) {
        v0 = g_cand2[w * KKEY + lane];
        v1 = g_cand2[w * KKEY + 32 + lane];
    }
    for (int nl = 8; nl > 1; nl >>= 1) {
        int half = nl >> 1;
        __syncthreads();
        if (w >= half && w < nl) {
            sx[(w - half) * 64 + lane] = v0;
            sx[(w - half) * 64 + 32 + lane] = v1;
        }
        __syncthreads();
        if (w < half) {
            u64 b0 = sx[w * 64 + lane];
            u64 b1 = sx[w * 64 + 32 + lane];
            warp_merge64(v0, v1, b0, b1, lane);
        }
    }
    if (w == 0) {
        sidx[lane]      = (int)(~(unsigned int)v0);
        sidx[lane + 32] = (int)(~(unsigned int)v1);
    }
    __syncthreads();

    // fused gather: out[b,k,c] = src_pts[b, c, idx[k]]   (8,64,6) row-major
#pragma unroll
    for (int o = t; o < 8 * KKEY * 6; o += 512) {
        int c = o % 6;
        int k = (o / 6) & (KKEY - 1);
        int b = o / (6 * KKEY);
        out[o] = src[(b * 6 + c) * N_PTS + sidx[k]];
    }

    __syncthreads();
    if (t == 0) g_done = 0u;   // reset for graph replay; elected block is last
}

// ---------------------------------------------------------------------------
extern "C" void kernel_launch(void* const* d_in, const int* in_sizes, int n_in,
                              void* d_out, int out_size)
{
    const float* src = (const float*)d_in[0];   // src_pts (8,6,65536)
    // d_in[1] = tgt_pts (unused)
    const float* W1 = (const float*)d_in[2];
    const float* b1 = (const float*)d_in[3];
    const float* W2 = (const float*)d_in[4];
    const float* b2 = (const float*)d_in[5];
    const float* Wa = (const float*)d_in[6];
    const float* ba = (const float*)d_in[7];
    const float* Wb = (const float*)d_in[8];
    const float* bb = (const float*)d_in[9];
    const float* Wc = (const float*)d_in[10];
    const float* bc = (const float*)d_in[11];
    float* out = (float*)d_out;

    score_kernel<<<GRID_SCORE, NT>>>(
        src, W1, b1, W2, b2, Wa, ba, Wb, bb, Wc, bc);
    tail_kernel<<<8, 512>>>(src, out);
}